// round 13
// baseline (speedup 1.0000x reference)
#include <cuda_runtime.h>

// Problem constants
#define NB 32
#define NH 480
#define NW 640
#define HW (NH * NW)            // 307200 pixels per channel plane
#define PIX4 (HW / 4)           // 76800 float4 pixels per plane
#define THREADS 256
#define BLOCKS_PER_IMG 300      // PIX4 / THREADS
#define NGROUPS 4
#define IMGS_PER_GROUP 8        // NB / NGROUPS
#define GRID_G (IMGS_PER_GROUP * BLOCKS_PER_IMG)   // 2400 blocks per kernel

// Per-block partial sums — every slot written every replay, no init needed.
__device__ float g_partial[NB * BLOCKS_PER_IMG];

// ---------------------------------------------------------------------------
// Reduce for one 8-image group. Trigger is issued ONLY AFTER the partial sum
// is globally visible (store + threadfence), so the dependent color kernel's
// cudaGridDependencySynchronize() ordering is correct.
// ---------------------------------------------------------------------------
__global__ void __launch_bounds__(THREADS)
reduce_group_kernel(const float* __restrict__ x,
                    const float* __restrict__ brightness_f,
                    int img_base) {
    const int b   = blockIdx.x;
    const int img = img_base + b / BLOCKS_PER_IMG;
    const int cb  = b % BLOCKS_PER_IMG;
    const int p4  = cb * THREADS + threadIdx.x;

    const float4* base = (const float4*)(x + (size_t)img * 3 * HW);
    const float bf = brightness_f[img];

    float4 r4 = base[p4];
    float4 g4 = base[p4 + PIX4];
    float4 b4 = base[p4 + 2 * PIX4];

    float s = 0.0f;
    {
        float r = __saturatef(r4.x * bf), g = __saturatef(g4.x * bf), b_ = __saturatef(b4.x * bf);
        s += fmaf(0.114f, b_, fmaf(0.587f, g, 0.299f * r));
        r = __saturatef(r4.y * bf); g = __saturatef(g4.y * bf); b_ = __saturatef(b4.y * bf);
        s += fmaf(0.114f, b_, fmaf(0.587f, g, 0.299f * r));
        r = __saturatef(r4.z * bf); g = __saturatef(g4.z * bf); b_ = __saturatef(b4.z * bf);
        s += fmaf(0.114f, b_, fmaf(0.587f, g, 0.299f * r));
        r = __saturatef(r4.w * bf); g = __saturatef(g4.w * bf); b_ = __saturatef(b4.w * bf);
        s += fmaf(0.114f, b_, fmaf(0.587f, g, 0.299f * r));
    }

    #pragma unroll
    for (int off = 16; off > 0; off >>= 1)
        s += __shfl_down_sync(0xFFFFFFFFu, s, off);

    __shared__ float warp_sums[THREADS / 32];
    const int lane = threadIdx.x & 31;
    const int wid  = threadIdx.x >> 5;
    if (lane == 0) warp_sums[wid] = s;
    __syncthreads();

    if (wid == 0) {
        float v = (lane < THREADS / 32) ? warp_sums[lane] : 0.0f;
        #pragma unroll
        for (int off = 4; off > 0; off >>= 1)
            v += __shfl_down_sync(0xFFFFFFFFu, v, off);
        if (lane == 0) {
            g_partial[img * BLOCKS_PER_IMG + cb] = v;
            __threadfence();
        }
    }
    __syncthreads();

    // Partial is globally visible -> safe to let the color kernel proceed.
    cudaTriggerProgrammaticLaunchCompletion();
}

// ---------------------------------------------------------------------------
// Color for one 8-image group. x reads are L2-hot (streamed by the paired
// reduce kernel microseconds earlier). Early trigger lets the NEXT group's
// reduce overlap (no data dependency); sync before consuming partials.
// ---------------------------------------------------------------------------
__global__ void __launch_bounds__(THREADS)
color_group_kernel(const float* __restrict__ x,
                   const float* __restrict__ brightness_f,
                   const float* __restrict__ contrast_f,
                   const float* __restrict__ saturation_f,
                   const float* __restrict__ hue_f,
                   float* __restrict__ out,
                   int img_base) {
    const int b   = blockIdx.x;
    const int img = img_base + b / BLOCKS_PER_IMG;
    const int p4  = (b % BLOCKS_PER_IMG) * THREADS + threadIdx.x;

    const size_t img_off = (size_t)img * 3 * HW;
    const float4* src = (const float4*)(x + img_off);
    float4* dst = (float4*)(out + img_off);

    // Front-issue x loads (independent of reduce results; L2-hot).
    float4 r4 = src[p4];
    float4 g4 = src[p4 + PIX4];
    float4 b4 = src[p4 + 2 * PIX4];

    const float bf  = brightness_f[img];
    const float cf  = contrast_f[img];
    const float sf  = saturation_f[img];
    const float hf6 = 6.0f * hue_f[img];

    // Next group's reduce may start now (disjoint data).
    cudaTriggerProgrammaticLaunchCompletion();

    // Wait for this group's reduce grid before touching g_partial.
    cudaGridDependencySynchronize();

    // ---- per-image mean from partials (all L2-hit) ----
    __shared__ float warp_sums[THREADS / 32];
    __shared__ float s_mean;
    {
        const float* part = g_partial + img * BLOCKS_PER_IMG;
        float v = 0.0f;
        for (int t = threadIdx.x; t < BLOCKS_PER_IMG; t += THREADS)
            v += part[t];
        #pragma unroll
        for (int off = 16; off > 0; off >>= 1)
            v += __shfl_down_sync(0xFFFFFFFFu, v, off);
        const int lane = threadIdx.x & 31;
        const int wid  = threadIdx.x >> 5;
        if (lane == 0) warp_sums[wid] = v;
        __syncthreads();
        if (threadIdx.x == 0) {
            float m = 0.0f;
            #pragma unroll
            for (int w = 0; w < THREADS / 32; w++) m += warp_sums[w];
            s_mean = m * (1.0f / (float)HW);
        }
        __syncthreads();
    }

    const float cm   = (1.0f - cf) * s_mean;
    const float omsf = 1.0f - sf;

    float ro[4], go[4], bo[4];
    const float* rp = &r4.x;
    const float* gp = &g4.x;
    const float* bp = &b4.x;

    #pragma unroll
    for (int k = 0; k < 4; k++) {
        float r = __saturatef(rp[k] * bf);
        float g = __saturatef(gp[k] * bf);
        float b = __saturatef(bp[k] * bf);
        r = __saturatef(fmaf(cf, r, cm));
        g = __saturatef(fmaf(cf, g, cm));
        b = __saturatef(fmaf(cf, b, cm));
        float gray = fmaf(0.114f, b, fmaf(0.587f, g, 0.299f * r));
        float sg = omsf * gray;
        r = __saturatef(fmaf(sf, r, sg));
        g = __saturatef(fmaf(sf, g, sg));
        b = __saturatef(fmaf(sf, b, sg));

        float maxc = fmaxf(r, fmaxf(g, b));
        float minc = fminf(r, fminf(g, b));
        float chroma = maxc - minc;
        float crd = (chroma == 0.0f) ? 1.0f : chroma;
        float rcp = __fdividef(1.0f, crd);

        float hr;                                 // raw hue * 6, in (-1, 5)
        if (maxc == r)      hr = (g - b) * rcp;
        else if (maxc == g) hr = fmaf(b - r, rcp, 2.0f);
        else                hr = fmaf(r - g, rcp, 4.0f);

        float h6 = hr + hf6;                      // in (-2.8, 6.8)
        if (h6 < 0.0f)       h6 += 6.0f;
        else if (h6 >= 6.0f) h6 -= 6.0f;

        // triangular channel responses (== reference p/q/t table, all sectors)
        float dr = fabsf(h6 - 3.0f);
        float fr = __saturatef(2.0f - dr);
        float tg = fabsf(h6 - 5.0f);
        float fg = __saturatef(2.0f - fminf(tg, 6.0f - tg));
        float tb = fabsf(h6 - 1.0f);
        float fb = __saturatef(2.0f - fminf(tb, 6.0f - tb));

        ro[k] = fmaf(-chroma, fr, maxc);
        go[k] = fmaf(-chroma, fg, maxc);
        bo[k] = fmaf(-chroma, fb, maxc);
    }

    __stcs(&dst[p4],            make_float4(ro[0], ro[1], ro[2], ro[3]));
    __stcs(&dst[p4 + PIX4],     make_float4(go[0], go[1], go[2], go[3]));
    __stcs(&dst[p4 + 2 * PIX4], make_float4(bo[0], bo[1], bo[2], bo[3]));
}

extern "C" void kernel_launch(void* const* d_in, const int* in_sizes, int n_in,
                              void* d_out, int out_size) {
    const float* x  = (const float*)d_in[0];
    const float* bf = (const float*)d_in[1];
    const float* cf = (const float*)d_in[2];
    const float* sf = (const float*)d_in[3];
    const float* hf = (const float*)d_in[4];
    float* out = (float*)d_out;

    cudaLaunchAttribute attr[1];
    attr[0].id = cudaLaunchAttributeProgrammaticStreamSerialization;
    attr[0].val.programmaticStreamSerializationAllowed = 1;

    bool pdl_ok = true;
    for (int g = 0; g < NGROUPS && pdl_ok; g++) {
        const int img_base = g * IMGS_PER_GROUP;

        cudaLaunchConfig_t cfgR = {};
        cfgR.gridDim  = dim3(GRID_G, 1, 1);
        cfgR.blockDim = dim3(THREADS, 1, 1);
        cfgR.attrs = attr;
        cfgR.numAttrs = 1;
        if (cudaLaunchKernelEx(&cfgR, reduce_group_kernel, x, bf, img_base)
            != cudaSuccess) { pdl_ok = false; break; }

        cudaLaunchConfig_t cfgC = {};
        cfgC.gridDim  = dim3(GRID_G, 1, 1);
        cfgC.blockDim = dim3(THREADS, 1, 1);
        cfgC.attrs = attr;
        cfgC.numAttrs = 1;
        if (cudaLaunchKernelEx(&cfgC, color_group_kernel, x, bf, cf, sf, hf, out, img_base)
            != cudaSuccess) { pdl_ok = false; break; }
    }

    if (!pdl_ok) {
        // Fallback: plain serialized launches (correct, slower).
        for (int g = 0; g < NGROUPS; g++) {
            const int img_base = g * IMGS_PER_GROUP;
            reduce_group_kernel<<<GRID_G, THREADS>>>(x, bf, img_base);
            color_group_kernel<<<GRID_G, THREADS>>>(x, bf, cf, sf, hf, out, img_base);
        }
    }
}

// round 14
// speedup vs baseline: 1.0360x; 1.0360x over previous
#include <cuda_runtime.h>

// Problem constants
#define NB 32
#define NH 480
#define NW 640
#define HW (NH * NW)            // 307200 pixels per channel plane
#define PIX4 (HW / 4)           // 76800 float4 pixels per plane
#define THREADS 256
#define BLOCKS_PER_IMG 300      // PIX4 / THREADS
#define NGROUPS 2
#define IMGS_PER_GROUP 16       // NB / NGROUPS
#define GRID_G (IMGS_PER_GROUP * BLOCKS_PER_IMG)   // 4800 blocks per kernel

// Per-block partial sums — every slot written every replay, no init needed.
__device__ float g_partial[NB * BLOCKS_PER_IMG];

// ---------------------------------------------------------------------------
// Reduce for one 16-image group. Trigger fires only AFTER the partial sum is
// globally visible, so the dependent color kernel's sync ordering is correct.
// No grid-dependency sync here: overlaps the previous color kernel freely.
// ---------------------------------------------------------------------------
__global__ void __launch_bounds__(THREADS)
reduce_group_kernel(const float* __restrict__ x,
                    const float* __restrict__ brightness_f,
                    int img_base) {
    const int b   = blockIdx.x;
    const int img = img_base + b / BLOCKS_PER_IMG;
    const int cb  = b % BLOCKS_PER_IMG;
    const int p4  = cb * THREADS + threadIdx.x;

    const float4* base = (const float4*)(x + (size_t)img * 3 * HW);
    const float bf = brightness_f[img];

    float4 r4 = base[p4];
    float4 g4 = base[p4 + PIX4];
    float4 b4 = base[p4 + 2 * PIX4];

    float s = 0.0f;
    {
        float r = __saturatef(r4.x * bf), g = __saturatef(g4.x * bf), b_ = __saturatef(b4.x * bf);
        s += fmaf(0.114f, b_, fmaf(0.587f, g, 0.299f * r));
        r = __saturatef(r4.y * bf); g = __saturatef(g4.y * bf); b_ = __saturatef(b4.y * bf);
        s += fmaf(0.114f, b_, fmaf(0.587f, g, 0.299f * r));
        r = __saturatef(r4.z * bf); g = __saturatef(g4.z * bf); b_ = __saturatef(b4.z * bf);
        s += fmaf(0.114f, b_, fmaf(0.587f, g, 0.299f * r));
        r = __saturatef(r4.w * bf); g = __saturatef(g4.w * bf); b_ = __saturatef(b4.w * bf);
        s += fmaf(0.114f, b_, fmaf(0.587f, g, 0.299f * r));
    }

    #pragma unroll
    for (int off = 16; off > 0; off >>= 1)
        s += __shfl_down_sync(0xFFFFFFFFu, s, off);

    __shared__ float warp_sums[THREADS / 32];
    const int lane = threadIdx.x & 31;
    const int wid  = threadIdx.x >> 5;
    if (lane == 0) warp_sums[wid] = s;
    __syncthreads();

    if (wid == 0) {
        float v = (lane < THREADS / 32) ? warp_sums[lane] : 0.0f;
        #pragma unroll
        for (int off = 4; off > 0; off >>= 1)
            v += __shfl_down_sync(0xFFFFFFFFu, v, off);
        if (lane == 0) {
            g_partial[img * BLOCKS_PER_IMG + cb] = v;
            __threadfence();
        }
    }
    __syncthreads();

    // Partial globally visible -> safe to let the color kernel proceed.
    cudaTriggerProgrammaticLaunchCompletion();
}

// ---------------------------------------------------------------------------
// Color for one 16-image group. x reads are L2-hot (streamed by the paired
// reduce kernel microseconds earlier). Early trigger lets the NEXT group's
// reduce overlap (no data dependency); sync before consuming partials.
// Reversed traversal: consume the group's hottest (most recent) tail first.
// ---------------------------------------------------------------------------
__global__ void __launch_bounds__(THREADS)
color_group_kernel(const float* __restrict__ x,
                   const float* __restrict__ brightness_f,
                   const float* __restrict__ contrast_f,
                   const float* __restrict__ saturation_f,
                   const float* __restrict__ hue_f,
                   float* __restrict__ out,
                   int img_base) {
    const int b   = GRID_G - 1 - blockIdx.x;          // reversed block id
    const int img = img_base + b / BLOCKS_PER_IMG;
    const int p4  = (b % BLOCKS_PER_IMG) * THREADS + threadIdx.x;

    const size_t img_off = (size_t)img * 3 * HW;
    const float4* src = (const float4*)(x + img_off);
    float4* dst = (float4*)(out + img_off);

    // Front-issue x loads (independent of reduce results; L2-hot).
    float4 r4 = src[p4];
    float4 g4 = src[p4 + PIX4];
    float4 b4 = src[p4 + 2 * PIX4];

    const float bf  = brightness_f[img];
    const float cf  = contrast_f[img];
    const float sf  = saturation_f[img];
    const float hf6 = 6.0f * hue_f[img];

    // Next group's reduce may start now (disjoint data).
    cudaTriggerProgrammaticLaunchCompletion();

    // Wait for this group's reduce grid before touching g_partial.
    cudaGridDependencySynchronize();

    // ---- per-image mean from partials (all L2-hit) ----
    __shared__ float warp_sums[THREADS / 32];
    __shared__ float s_mean;
    {
        const float* part = g_partial + img * BLOCKS_PER_IMG;
        float v = 0.0f;
        for (int t = threadIdx.x; t < BLOCKS_PER_IMG; t += THREADS)
            v += part[t];
        #pragma unroll
        for (int off = 16; off > 0; off >>= 1)
            v += __shfl_down_sync(0xFFFFFFFFu, v, off);
        const int lane = threadIdx.x & 31;
        const int wid  = threadIdx.x >> 5;
        if (lane == 0) warp_sums[wid] = v;
        __syncthreads();
        if (threadIdx.x == 0) {
            float m = 0.0f;
            #pragma unroll
            for (int w = 0; w < THREADS / 32; w++) m += warp_sums[w];
            s_mean = m * (1.0f / (float)HW);
        }
        __syncthreads();
    }

    const float cm   = (1.0f - cf) * s_mean;
    const float omsf = 1.0f - sf;

    float ro[4], go[4], bo[4];
    const float* rp = &r4.x;
    const float* gp = &g4.x;
    const float* bp = &b4.x;

    #pragma unroll
    for (int k = 0; k < 4; k++) {
        float r = __saturatef(rp[k] * bf);
        float g = __saturatef(gp[k] * bf);
        float b = __saturatef(bp[k] * bf);
        r = __saturatef(fmaf(cf, r, cm));
        g = __saturatef(fmaf(cf, g, cm));
        b = __saturatef(fmaf(cf, b, cm));
        float gray = fmaf(0.114f, b, fmaf(0.587f, g, 0.299f * r));
        float sg = omsf * gray;
        r = __saturatef(fmaf(sf, r, sg));
        g = __saturatef(fmaf(sf, g, sg));
        b = __saturatef(fmaf(sf, b, sg));

        float maxc = fmaxf(r, fmaxf(g, b));
        float minc = fminf(r, fminf(g, b));
        float chroma = maxc - minc;
        float crd = (chroma == 0.0f) ? 1.0f : chroma;
        float rcp = __fdividef(1.0f, crd);

        float hr;                                 // raw hue * 6, in (-1, 5)
        if (maxc == r)      hr = (g - b) * rcp;
        else if (maxc == g) hr = fmaf(b - r, rcp, 2.0f);
        else                hr = fmaf(r - g, rcp, 4.0f);

        float h6 = hr + hf6;                      // in (-2.8, 6.8)
        if (h6 < 0.0f)       h6 += 6.0f;
        else if (h6 >= 6.0f) h6 -= 6.0f;

        // triangular channel responses (== reference p/q/t table, all sectors)
        float dr = fabsf(h6 - 3.0f);
        float fr = __saturatef(2.0f - dr);
        float tg = fabsf(h6 - 5.0f);
        float fg = __saturatef(2.0f - fminf(tg, 6.0f - tg));
        float tb = fabsf(h6 - 1.0f);
        float fb = __saturatef(2.0f - fminf(tb, 6.0f - tb));

        ro[k] = fmaf(-chroma, fr, maxc);
        go[k] = fmaf(-chroma, fg, maxc);
        bo[k] = fmaf(-chroma, fb, maxc);
    }

    __stcs(&dst[p4],            make_float4(ro[0], ro[1], ro[2], ro[3]));
    __stcs(&dst[p4 + PIX4],     make_float4(go[0], go[1], go[2], go[3]));
    __stcs(&dst[p4 + 2 * PIX4], make_float4(bo[0], bo[1], bo[2], bo[3]));
}

extern "C" void kernel_launch(void* const* d_in, const int* in_sizes, int n_in,
                              void* d_out, int out_size) {
    const float* x  = (const float*)d_in[0];
    const float* bf = (const float*)d_in[1];
    const float* cf = (const float*)d_in[2];
    const float* sf = (const float*)d_in[3];
    const float* hf = (const float*)d_in[4];
    float* out = (float*)d_out;

    cudaLaunchAttribute attr[1];
    attr[0].id = cudaLaunchAttributeProgrammaticStreamSerialization;
    attr[0].val.programmaticStreamSerializationAllowed = 1;

    bool pdl_ok = true;
    for (int g = 0; g < NGROUPS && pdl_ok; g++) {
        const int img_base = g * IMGS_PER_GROUP;

        cudaLaunchConfig_t cfgR = {};
        cfgR.gridDim  = dim3(GRID_G, 1, 1);
        cfgR.blockDim = dim3(THREADS, 1, 1);
        cfgR.attrs = attr;
        cfgR.numAttrs = 1;
        if (cudaLaunchKernelEx(&cfgR, reduce_group_kernel, x, bf, img_base)
            != cudaSuccess) { pdl_ok = false; break; }

        cudaLaunchConfig_t cfgC = {};
        cfgC.gridDim  = dim3(GRID_G, 1, 1);
        cfgC.blockDim = dim3(THREADS, 1, 1);
        cfgC.attrs = attr;
        cfgC.numAttrs = 1;
        if (cudaLaunchKernelEx(&cfgC, color_group_kernel, x, bf, cf, sf, hf, out, img_base)
            != cudaSuccess) { pdl_ok = false; break; }
    }

    if (!pdl_ok) {
        // Fallback: plain serialized launches (correct, slower).
        for (int g = 0; g < NGROUPS; g++) {
            const int img_base = g * IMGS_PER_GROUP;
            reduce_group_kernel<<<GRID_G, THREADS>>>(x, bf, img_base);
            color_group_kernel<<<GRID_G, THREADS>>>(x, bf, cf, sf, hf, out, img_base);
        }
    }
}

// round 15
// speedup vs baseline: 1.1298x; 1.0905x over previous
#include <cuda_runtime.h>

// Problem constants
#define NB 32
#define NH 480
#define NW 640
#define HW (NH * NW)            // 307200 pixels per channel plane
#define PIX4 (HW / 4)           // 76800 float4 pixels per plane
#define THREADS 256
#define BLOCKS_PER_IMG 300      // chunk granularity (PIX4 / THREADS)

// Reduce kernel: 2 chunks per block
#define RPAIRS_PER_IMG 150
#define GRID_R (NB * RPAIRS_PER_IMG)      // 4800

// Color kernel: 3 chunks per block
#define CTRIOS_PER_IMG 100
#define GRID_C (NB * CTRIOS_PER_IMG)      // 3200

// Per-(half)block partial sums — every slot written every replay, no init.
__device__ float g_partial[GRID_R];
#define PARTS_PER_IMG RPAIRS_PER_IMG      // 150 partials per image

__device__ __forceinline__ float gray_sum4(const float4& r4, const float4& g4,
                                           const float4& b4, float bf) {
    float s = 0.0f;
    float r = __saturatef(r4.x * bf), g = __saturatef(g4.x * bf), b = __saturatef(b4.x * bf);
    s += fmaf(0.114f, b, fmaf(0.587f, g, 0.299f * r));
    r = __saturatef(r4.y * bf); g = __saturatef(g4.y * bf); b = __saturatef(b4.y * bf);
    s += fmaf(0.114f, b, fmaf(0.587f, g, 0.299f * r));
    r = __saturatef(r4.z * bf); g = __saturatef(g4.z * bf); b = __saturatef(b4.z * bf);
    s += fmaf(0.114f, b, fmaf(0.587f, g, 0.299f * r));
    r = __saturatef(r4.w * bf); g = __saturatef(g4.w * bf); b = __saturatef(b4.w * bf);
    s += fmaf(0.114f, b, fmaf(0.587f, g, 0.299f * r));
    return s;
}

// ---------------------------------------------------------------------------
// Pass 1: 2 chunks per block, 6 front-batched LDG.128 for MLP.
// ---------------------------------------------------------------------------
__global__ void __launch_bounds__(THREADS)
reduce_mean_kernel(const float* __restrict__ x,
                   const float* __restrict__ brightness_f) {
    const int img  = blockIdx.x / RPAIRS_PER_IMG;
    const int pair = blockIdx.x % RPAIRS_PER_IMG;
    const int p4a  = (pair * 2) * THREADS + threadIdx.x;
    const int p4b  = p4a + THREADS;

    const float4* base = (const float4*)(x + (size_t)img * 3 * HW);
    const float bf = brightness_f[img];

    // 6 independent loads in flight
    float4 r4a = base[p4a];
    float4 g4a = base[p4a + PIX4];
    float4 b4a = base[p4a + 2 * PIX4];
    float4 r4b = base[p4b];
    float4 g4b = base[p4b + PIX4];
    float4 b4b = base[p4b + 2 * PIX4];

    float s = gray_sum4(r4a, g4a, b4a, bf) + gray_sum4(r4b, g4b, b4b, bf);

    #pragma unroll
    for (int off = 16; off > 0; off >>= 1)
        s += __shfl_down_sync(0xFFFFFFFFu, s, off);

    __shared__ float warp_sums[THREADS / 32];
    const int lane = threadIdx.x & 31;
    const int wid  = threadIdx.x >> 5;
    if (lane == 0) warp_sums[wid] = s;
    __syncthreads();

    if (wid == 0) {
        float v = (lane < THREADS / 32) ? warp_sums[lane] : 0.0f;
        #pragma unroll
        for (int off = 4; off > 0; off >>= 1)
            v += __shfl_down_sync(0xFFFFFFFFu, v, off);
        if (lane == 0) g_partial[blockIdx.x] = v;
    }

    cudaTriggerProgrammaticLaunchCompletion();
}

// ---------------------------------------------------------------------------
// One 4-pixel color transform.
// ---------------------------------------------------------------------------
__device__ __forceinline__ void color4(const float4& r4, const float4& g4, const float4& b4,
                                       float bf, float cf, float sf, float hf6,
                                       float cm, float omsf,
                                       float4& rout, float4& gout, float4& bout) {
    float ro[4], go[4], bo[4];
    const float* rp = &r4.x;
    const float* gp = &g4.x;
    const float* bp = &b4.x;

    #pragma unroll
    for (int k = 0; k < 4; k++) {
        float r = __saturatef(rp[k] * bf);
        float g = __saturatef(gp[k] * bf);
        float b = __saturatef(bp[k] * bf);
        r = __saturatef(fmaf(cf, r, cm));
        g = __saturatef(fmaf(cf, g, cm));
        b = __saturatef(fmaf(cf, b, cm));
        float gray = fmaf(0.114f, b, fmaf(0.587f, g, 0.299f * r));
        float sg = omsf * gray;
        r = __saturatef(fmaf(sf, r, sg));
        g = __saturatef(fmaf(sf, g, sg));
        b = __saturatef(fmaf(sf, b, sg));

        float maxc = fmaxf(r, fmaxf(g, b));
        float minc = fminf(r, fminf(g, b));
        float chroma = maxc - minc;
        float crd = (chroma == 0.0f) ? 1.0f : chroma;
        float rcp = __fdividef(1.0f, crd);

        float hr;                                 // raw hue * 6, in (-1, 5)
        if (maxc == r)      hr = (g - b) * rcp;
        else if (maxc == g) hr = fmaf(b - r, rcp, 2.0f);
        else                hr = fmaf(r - g, rcp, 4.0f);

        float h6 = hr + hf6;                      // in (-2.8, 6.8)
        if (h6 < 0.0f)       h6 += 6.0f;
        else if (h6 >= 6.0f) h6 -= 6.0f;

        // triangular channel responses (== reference p/q/t table, all sectors)
        float dr = fabsf(h6 - 3.0f);
        float fr = __saturatef(2.0f - dr);
        float tg = fabsf(h6 - 5.0f);
        float fg = __saturatef(2.0f - fminf(tg, 6.0f - tg));
        float tb = fabsf(h6 - 1.0f);
        float fb = __saturatef(2.0f - fminf(tb, 6.0f - tb));

        ro[k] = fmaf(-chroma, fr, maxc);
        go[k] = fmaf(-chroma, fg, maxc);
        bo[k] = fmaf(-chroma, fb, maxc);
    }
    rout = make_float4(ro[0], ro[1], ro[2], ro[3]);
    gout = make_float4(go[0], go[1], go[2], go[3]);
    bout = make_float4(bo[0], bo[1], bo[2], bo[3]);
}

// ---------------------------------------------------------------------------
// Pass 2: 3 chunks per block, 9 front-batched LDG.128 for MLP.
// ---------------------------------------------------------------------------
__global__ void __launch_bounds__(THREADS)
color_kernel(const float* __restrict__ x,
             const float* __restrict__ brightness_f,
             const float* __restrict__ contrast_f,
             const float* __restrict__ saturation_f,
             const float* __restrict__ hue_f,
             float* __restrict__ out) {
    const int rb   = GRID_C - 1 - blockIdx.x;        // reversed block id
    const int img  = rb / CTRIOS_PER_IMG;
    const int trio = rb % CTRIOS_PER_IMG;
    const int p4a  = (trio * 3) * THREADS + threadIdx.x;
    const int p4b  = p4a + THREADS;
    const int p4c  = p4b + THREADS;

    const size_t img_off = (size_t)img * 3 * HW;
    const float4* src = (const float4*)(x + img_off);
    float4* dst = (float4*)(out + img_off);

    // 9 independent loads in flight (L2-hot tail first).
    float4 r4a = src[p4a];
    float4 g4a = src[p4a + PIX4];
    float4 b4a = src[p4a + 2 * PIX4];
    float4 r4b = src[p4b];
    float4 g4b = src[p4b + PIX4];
    float4 b4b = src[p4b + 2 * PIX4];
    float4 r4c = src[p4c];
    float4 g4c = src[p4c + PIX4];
    float4 b4c = src[p4c + 2 * PIX4];

    const float bf  = brightness_f[img];
    const float cf  = contrast_f[img];
    const float sf  = saturation_f[img];
    const float hf6 = 6.0f * hue_f[img];

    // Wait for the reduce grid before touching g_partial.
    cudaGridDependencySynchronize();

    // ---- per-image mean from partials (all L2-hit) ----
    __shared__ float warp_sums[THREADS / 32];
    __shared__ float s_mean;
    {
        const float* part = g_partial + img * PARTS_PER_IMG;
        float v = 0.0f;
        for (int t = threadIdx.x; t < PARTS_PER_IMG; t += THREADS)
            v += part[t];
        #pragma unroll
        for (int off = 16; off > 0; off >>= 1)
            v += __shfl_down_sync(0xFFFFFFFFu, v, off);
        const int lane = threadIdx.x & 31;
        const int wid  = threadIdx.x >> 5;
        if (lane == 0) warp_sums[wid] = v;
        __syncthreads();
        if (threadIdx.x == 0) {
            float m = 0.0f;
            #pragma unroll
            for (int w = 0; w < THREADS / 32; w++) m += warp_sums[w];
            s_mean = m * (1.0f / (float)HW);
        }
        __syncthreads();
    }

    const float cm   = (1.0f - cf) * s_mean;
    const float omsf = 1.0f - sf;

    float4 rr, gg, bb;
    color4(r4a, g4a, b4a, bf, cf, sf, hf6, cm, omsf, rr, gg, bb);
    __stcs(&dst[p4a],            rr);
    __stcs(&dst[p4a + PIX4],     gg);
    __stcs(&dst[p4a + 2 * PIX4], bb);

    color4(r4b, g4b, b4b, bf, cf, sf, hf6, cm, omsf, rr, gg, bb);
    __stcs(&dst[p4b],            rr);
    __stcs(&dst[p4b + PIX4],     gg);
    __stcs(&dst[p4b + 2 * PIX4], bb);

    color4(r4c, g4c, b4c, bf, cf, sf, hf6, cm, omsf, rr, gg, bb);
    __stcs(&dst[p4c],            rr);
    __stcs(&dst[p4c + PIX4],     gg);
    __stcs(&dst[p4c + 2 * PIX4], bb);
}

extern "C" void kernel_launch(void* const* d_in, const int* in_sizes, int n_in,
                              void* d_out, int out_size) {
    const float* x  = (const float*)d_in[0];
    const float* bf = (const float*)d_in[1];
    const float* cf = (const float*)d_in[2];
    const float* sf = (const float*)d_in[3];
    const float* hf = (const float*)d_in[4];
    float* out = (float*)d_out;

    reduce_mean_kernel<<<GRID_R, THREADS>>>(x, bf);

    // PDL launch: color's x-loads overlap the reduce tail.
    cudaLaunchConfig_t cfg = {};
    cfg.gridDim  = dim3(GRID_C, 1, 1);
    cfg.blockDim = dim3(THREADS, 1, 1);
    cfg.dynamicSmemBytes = 0;
    cudaLaunchAttribute attr[1];
    attr[0].id = cudaLaunchAttributeProgrammaticStreamSerialization;
    attr[0].val.programmaticStreamSerializationAllowed = 1;
    cfg.attrs = attr;
    cfg.numAttrs = 1;

    cudaError_t e = cudaLaunchKernelEx(&cfg, color_kernel, x, bf, cf, sf, hf, out);
    if (e != cudaSuccess) {
        color_kernel<<<GRID_C, THREADS>>>(x, bf, cf, sf, hf, out);
    }
}